// round 4
// baseline (speedup 1.0000x reference)
#include <cuda_runtime.h>
#include <math.h>

// ---------------------------------------------------------------------------
// QuickPatternMatchingLoss
//   out[b] = log( (1/ls) * sum_{l: mask} sum_o ss_hmm[o,l] *
//                 softmax_o( W[:, :20] . x[b,1:,l] + slog[:,l] ) )
//   slog[o,l] = b[o] + sum_h W[o,20+h] * seq_hmm[h,l]
//   mask[b,l] = ( max_{c>=1} x[b,c,l] > x[b,0,l] )
//
// R4 layout: warp-per-row, 4 rows per CTA, grid = B/4. Each warp loops over
// its row's column chunks (Lv/32 iterations x 21 LDG.128) and does ONE shfl
// reduce at the end -> epilogue tail amortized over 4x the DRAM traffic.
// All small operands (W, slog, ss_hmm) staged in smem once per CTA so the
// steady-state load stream is exactly the 21 x-channel LDG.128s (R3 showed
// extra scalar LDGs in the loop poison LSU issue order).
// ---------------------------------------------------------------------------

#define MAX_LS 1024
__device__ float g_slog[3 * 2048];   // fallback path scratch

// ---- fused main kernel ------------------------------------------------------
template <int NC>
__global__ void __launch_bounds__(128, 6)
qpml_kernel(const float* __restrict__ x,
            const float* __restrict__ seq_hmm,
            const float* __restrict__ ss_hmm,
            const float* __restrict__ W,
            const float* __restrict__ bvec,
            float* __restrict__ out,
            int B, int L, int H, int wstride, int nc_rt)
{
    const int C = (NC > 0) ? NC : nc_rt;
    const int t = threadIdx.x;

    __shared__ __align__(16) float s_sl[3][MAX_LS];   // batch-invariant logits
    __shared__ __align__(16) float s_h[3][MAX_LS];    // ss_hmm
    __shared__ float sW0[32], sW1[32], sW2[32];       // W[:, :20]

    if (t < 20) {
        sW0[t] = __ldg(&W[0 * wstride + t]);
        sW1[t] = __ldg(&W[1 * wstride + t]);
        sW2[t] = __ldg(&W[2 * wstride + t]);
    }
    {   // per-CTA slog (seq_hmm is 60 KB, L2-resident across 1024 CTAs)
        float b0 = __ldg(&bvec[0]), b1 = __ldg(&bvec[1]), b2 = __ldg(&bvec[2]);
        for (int l = t; l < L; l += 128) {
            float s0 = b0, s1 = b1, s2 = b2;
            for (int h = 0; h < H; ++h) {
                float v = __ldg(&seq_hmm[h * L + l]);
                s0 = fmaf(__ldg(&W[0 * wstride + 20 + h]), v, s0);
                s1 = fmaf(__ldg(&W[1 * wstride + 20 + h]), v, s1);
                s2 = fmaf(__ldg(&W[2 * wstride + 20 + h]), v, s2);
            }
            s_sl[0][l] = s0;  s_sl[1][l] = s1;  s_sl[2][l] = s2;
            s_h[0][l] = __ldg(&ss_hmm[0 * L + l]);
            s_h[1][l] = __ldg(&ss_hmm[1 * L + l]);
            s_h[2][l] = __ldg(&ss_hmm[2 * L + l]);
        }
    }
    __syncthreads();   // only barrier

    const int warp = t >> 5, lane = t & 31;
    const int b = blockIdx.x * 4 + warp;          // one row per warp
    if (b >= B) return;

    const float4* xb = (const float4*)(x + (size_t)b * (size_t)C * (size_t)L);
    const int Lv = L >> 2;

    float contrib = 0.f, cnt = 0.f;

    for (int i = lane; i < Lv; i += 32) {
        // gap channel
        float4 v0 = __ldg(&xb[i]);
        float x0[4] = {v0.x, v0.y, v0.z, v0.w};
        float mx[4] = {-INFINITY, -INFINITY, -INFINITY, -INFINITY};
        float a0[4] = {0.f, 0.f, 0.f, 0.f};
        float a1[4] = {0.f, 0.f, 0.f, 0.f};
        float a2[4] = {0.f, 0.f, 0.f, 0.f};

        #pragma unroll
        for (int c = 1; c < C; ++c) {
            float4 v = __ldg(&xb[c * Lv + i]);
            float vv[4] = {v.x, v.y, v.z, v.w};
            float w0 = sW0[c - 1], w1 = sW1[c - 1], w2 = sW2[c - 1];
            #pragma unroll
            for (int j = 0; j < 4; ++j) {
                mx[j] = fmaxf(mx[j], vv[j]);
                a0[j] = fmaf(w0, vv[j], a0[j]);
                a1[j] = fmaf(w1, vv[j], a1[j]);
                a2[j] = fmaf(w2, vv[j], a2[j]);
            }
        }

        float4 sl0 = ((const float4*)s_sl[0])[i];
        float4 sl1 = ((const float4*)s_sl[1])[i];
        float4 sl2 = ((const float4*)s_sl[2])[i];
        float4 h0  = ((const float4*)s_h[0])[i];
        float4 h1  = ((const float4*)s_h[1])[i];
        float4 h2  = ((const float4*)s_h[2])[i];
        float sla0[4] = {sl0.x, sl0.y, sl0.z, sl0.w};
        float sla1[4] = {sl1.x, sl1.y, sl1.z, sl1.w};
        float sla2[4] = {sl2.x, sl2.y, sl2.z, sl2.w};
        float ha0[4]  = {h0.x, h0.y, h0.z, h0.w};
        float ha1[4]  = {h1.x, h1.y, h1.z, h1.w};
        float ha2[4]  = {h2.x, h2.y, h2.z, h2.w};

        #pragma unroll
        for (int j = 0; j < 4; ++j) {
            float e0 = __expf(a0[j] + sla0[j]);
            float e1 = __expf(a1[j] + sla1[j]);
            float e2 = __expf(a2[j] + sla2[j]);
            float num = ha0[j] * e0 + ha1[j] * e1 + ha2[j] * e2;
            float den = e0 + e1 + e2;
            bool m = mx[j] > x0[j];
            contrib += m ? __fdividef(num, den) : 0.f;
            cnt     += m ? 1.f : 0.f;
        }
    }

    // warp-only reduction (no smem, no barrier)
    #pragma unroll
    for (int off = 16; off > 0; off >>= 1) {
        contrib += __shfl_down_sync(0xffffffffu, contrib, off);
        cnt     += __shfl_down_sync(0xffffffffu, cnt, off);
    }
    if (lane == 0) out[b] = logf(contrib / cnt);
}

// ---- fallback for odd shapes ------------------------------------------------
__global__ void slog_kernel(const float* __restrict__ seq_hmm,
                            const float* __restrict__ W,
                            const float* __restrict__ bvec,
                            int L, int H, int wstride)
{
    int l = blockIdx.x * blockDim.x + threadIdx.x;
    if (l >= L) return;
    float s0 = bvec[0], s1 = bvec[1], s2 = bvec[2];
    for (int h = 0; h < H; ++h) {
        float v = __ldg(&seq_hmm[h * L + l]);
        s0 = fmaf(__ldg(&W[0 * wstride + 20 + h]), v, s0);
        s1 = fmaf(__ldg(&W[1 * wstride + 20 + h]), v, s1);
        s2 = fmaf(__ldg(&W[2 * wstride + 20 + h]), v, s2);
    }
    g_slog[0 * L + l] = s0;
    g_slog[1 * L + l] = s1;
    g_slog[2 * L + l] = s2;
}

__global__ void qpml_kernel_scalar(const float* __restrict__ x,
                                   const float* __restrict__ ss_hmm,
                                   const float* __restrict__ W,
                                   float* __restrict__ out,
                                   int L, int C, int wstride)
{
    const int b = blockIdx.x;
    const int t = threadIdx.x;
    const float* xb = x + (size_t)b * (size_t)C * (size_t)L;

    float contrib = 0.f, cnt = 0.f;
    for (int l = t; l < L; l += blockDim.x) {
        float x0 = xb[l];
        float mx = -INFINITY;
        float a0 = 0.f, a1 = 0.f, a2 = 0.f;
        for (int c = 1; c < C; ++c) {
            float v = xb[c * L + l];
            mx = fmaxf(mx, v);
            a0 = fmaf(W[0 * wstride + c - 1], v, a0);
            a1 = fmaf(W[1 * wstride + c - 1], v, a1);
            a2 = fmaf(W[2 * wstride + c - 1], v, a2);
        }
        float e0 = __expf(a0 + g_slog[0 * L + l]);
        float e1 = __expf(a1 + g_slog[1 * L + l]);
        float e2 = __expf(a2 + g_slog[2 * L + l]);
        float num = ss_hmm[0 * L + l] * e0 + ss_hmm[1 * L + l] * e1
                  + ss_hmm[2 * L + l] * e2;
        if (mx > x0) { contrib += num / (e0 + e1 + e2); cnt += 1.f; }
    }
    #pragma unroll
    for (int off = 16; off > 0; off >>= 1) {
        contrib += __shfl_down_sync(0xffffffffu, contrib, off);
        cnt     += __shfl_down_sync(0xffffffffu, cnt, off);
    }
    __shared__ float rs[2][32];
    int nw = (blockDim.x + 31) >> 5;
    if ((t & 31) == 0) { rs[0][t >> 5] = contrib; rs[1][t >> 5] = cnt; }
    __syncthreads();
    if (t == 0) {
        float s = 0.f, c = 0.f;
        for (int w = 0; w < nw; ++w) { s += rs[0][w]; c += rs[1][w]; }
        out[b] = logf(s / c);
    }
}

extern "C" void kernel_launch(void* const* d_in, const int* in_sizes, int n_in,
                              void* d_out, int out_size)
{
    const float* x       = (const float*)d_in[0];   // [B, 21, L]
    const float* seq_hmm = (const float*)d_in[1];   // [H, L]
    const float* ss_hmm  = (const float*)d_in[2];   // [3, L]
    const float* W       = (const float*)d_in[3];   // [3, 20+H]
    const float* bvec    = (const float*)d_in[4];   // [3]
    float* out = (float*)d_out;

    const int B       = out_size;                   // 4096
    const int L       = in_sizes[2] / 3;            // 512
    const int H       = in_sizes[1] / L;            // 30
    const int C       = in_sizes[0] / (B * L);      // 21
    const int wstride = in_sizes[3] / 3;            // 20 + H = 50

    if ((L & 3) == 0 && L <= MAX_LS) {
        int grid = (B + 3) / 4;                     // 4 rows per CTA (warp each)
        if (C == 21)
            qpml_kernel<21><<<grid, 128>>>(x, seq_hmm, ss_hmm, W, bvec, out,
                                           B, L, H, wstride, C);
        else
            qpml_kernel<0><<<grid, 128>>>(x, seq_hmm, ss_hmm, W, bvec, out,
                                          B, L, H, wstride, C);
    } else {
        slog_kernel<<<(L + 255) / 256, 256>>>(seq_hmm, W, bvec, L, H, wstride);
        qpml_kernel_scalar<<<B, 128>>>(x, ss_hmm, W, out, L, C, wstride);
    }
}

// round 5
// speedup vs baseline: 1.5621x; 1.5621x over previous
#include <cuda_runtime.h>
#include <math.h>

// ---------------------------------------------------------------------------
// QuickPatternMatchingLoss
//   out[b] = log( (1/ls) * sum_{l: mask} sum_o ss_hmm[o,l] *
//                 softmax_o( W[:, :20] . x[b,1:,l] + slog[:,l] ) )
//   slog[o,l] = b[o] + sum_h W[o,20+h] * seq_hmm[h,l]   (tiny prologue kernel)
//   mask[b,l] = ( max_{c>=1} x[b,c,l] > x[b,0,l] )
//
// R5 = best-known flat shape (R0: one CTA/row, 128 thr, 1 float4 chunk/thr,
// 21 LDG.128 stream, W in smem) + launch_bounds(128,6) for the 6th resident
// CTA (R3 proved regs fit) + table loads hoisted ahead of the channel loop.
// Loop/persistent variants are proven regressions (R2, R4) - do not revisit.
// ---------------------------------------------------------------------------

#define MAX_L 2048
__device__ float g_slog[3 * MAX_L];   // batch-invariant logits

// ---- prologue: slog[o,l] = b[o] + sum_h W[o,20+h] * seq_hmm[h,l] ----------
__global__ void slog_kernel(const float* __restrict__ seq_hmm,
                            const float* __restrict__ W,
                            const float* __restrict__ bvec,
                            int L, int H, int wstride)
{
    int l = blockIdx.x * blockDim.x + threadIdx.x;
    if (l >= L) return;
    float s0 = bvec[0], s1 = bvec[1], s2 = bvec[2];
    for (int h = 0; h < H; ++h) {
        float v = __ldg(&seq_hmm[h * L + l]);
        s0 = fmaf(__ldg(&W[0 * wstride + 20 + h]), v, s0);
        s1 = fmaf(__ldg(&W[1 * wstride + 20 + h]), v, s1);
        s2 = fmaf(__ldg(&W[2 * wstride + 20 + h]), v, s2);
    }
    g_slog[0 * L + l] = s0;
    g_slog[1 * L + l] = s1;
    g_slog[2 * L + l] = s2;
}

// ---- main kernel: one CTA per batch row, flat ------------------------------
template <int NC>
__global__ void __launch_bounds__(128, 6)
qpml_kernel(const float* __restrict__ x,
            const float* __restrict__ ss_hmm,
            const float* __restrict__ W,
            float* __restrict__ out,
            int L, int nc_rt, int wstride)
{
    const int b = blockIdx.x;
    const int t = threadIdx.x;
    const int C = (NC > 0) ? NC : nc_rt;
    const int Lv = L >> 2;

    __shared__ float sW0[20], sW1[20], sW2[20];
    if (t < 20) {
        sW0[t] = __ldg(&W[0 * wstride + t]);
        sW1[t] = __ldg(&W[1 * wstride + t]);
        sW2[t] = __ldg(&W[2 * wstride + t]);
    }
    __syncthreads();

    const float4* xb = (const float4*)(x + (size_t)b * (size_t)C * (size_t)L);

    float contrib = 0.f, cnt = 0.f;

    for (int i = t; i < Lv; i += 128) {
        // L2-hot table loads issued FIRST, in flight alongside the x stream.
        float4 sl0 = __ldg((const float4*)&g_slog[0 * L] + i);
        float4 sl1 = __ldg((const float4*)&g_slog[1 * L] + i);
        float4 sl2 = __ldg((const float4*)&g_slog[2 * L] + i);
        float4 h0  = __ldg((const float4*)&ss_hmm[0 * L] + i);
        float4 h1  = __ldg((const float4*)&ss_hmm[1 * L] + i);
        float4 h2  = __ldg((const float4*)&ss_hmm[2 * L] + i);

        // gap channel
        float4 v0 = __ldcs(&xb[i]);
        float x0[4] = {v0.x, v0.y, v0.z, v0.w};
        float mx[4] = {-INFINITY, -INFINITY, -INFINITY, -INFINITY};
        float a0[4] = {0.f, 0.f, 0.f, 0.f};
        float a1[4] = {0.f, 0.f, 0.f, 0.f};
        float a2[4] = {0.f, 0.f, 0.f, 0.f};

        #pragma unroll
        for (int c = 1; c < C; ++c) {
            float4 v = __ldcs(&xb[c * Lv + i]);
            float vv[4] = {v.x, v.y, v.z, v.w};
            float w0 = sW0[c - 1], w1 = sW1[c - 1], w2 = sW2[c - 1];
            #pragma unroll
            for (int j = 0; j < 4; ++j) {
                mx[j] = fmaxf(mx[j], vv[j]);
                a0[j] = fmaf(w0, vv[j], a0[j]);
                a1[j] = fmaf(w1, vv[j], a1[j]);
                a2[j] = fmaf(w2, vv[j], a2[j]);
            }
        }

        float sla0[4] = {sl0.x, sl0.y, sl0.z, sl0.w};
        float sla1[4] = {sl1.x, sl1.y, sl1.z, sl1.w};
        float sla2[4] = {sl2.x, sl2.y, sl2.z, sl2.w};
        float ha0[4]  = {h0.x, h0.y, h0.z, h0.w};
        float ha1[4]  = {h1.x, h1.y, h1.z, h1.w};
        float ha2[4]  = {h2.x, h2.y, h2.z, h2.w};

        #pragma unroll
        for (int j = 0; j < 4; ++j) {
            float e0 = __expf(a0[j] + sla0[j]);
            float e1 = __expf(a1[j] + sla1[j]);
            float e2 = __expf(a2[j] + sla2[j]);
            float num = ha0[j] * e0 + ha1[j] * e1 + ha2[j] * e2;
            float den = e0 + e1 + e2;
            bool m = mx[j] > x0[j];
            contrib += m ? __fdividef(num, den) : 0.f;
            cnt     += m ? 1.f : 0.f;
        }
    }

    // ---- block reduction (4 warps) ----
    #pragma unroll
    for (int off = 16; off > 0; off >>= 1) {
        contrib += __shfl_down_sync(0xffffffffu, contrib, off);
        cnt     += __shfl_down_sync(0xffffffffu, cnt, off);
    }
    __shared__ float rs[2][4];
    if ((t & 31) == 0) { rs[0][t >> 5] = contrib; rs[1][t >> 5] = cnt; }
    __syncthreads();
    if (t == 0) {
        float s = rs[0][0] + rs[0][1] + rs[0][2] + rs[0][3];
        float c = rs[1][0] + rs[1][1] + rs[1][2] + rs[1][3];
        out[b] = logf(s / c);
    }
}

// ---- scalar fallback for odd shapes ----------------------------------------
__global__ void qpml_kernel_scalar(const float* __restrict__ x,
                                   const float* __restrict__ ss_hmm,
                                   const float* __restrict__ W,
                                   float* __restrict__ out,
                                   int L, int C, int wstride)
{
    const int b = blockIdx.x;
    const int t = threadIdx.x;
    const float* xb = x + (size_t)b * (size_t)C * (size_t)L;

    float contrib = 0.f, cnt = 0.f;
    for (int l = t; l < L; l += blockDim.x) {
        float x0 = xb[l];
        float mx = -INFINITY;
        float a0 = 0.f, a1 = 0.f, a2 = 0.f;
        for (int c = 1; c < C; ++c) {
            float v = xb[c * L + l];
            mx = fmaxf(mx, v);
            a0 = fmaf(W[0 * wstride + c - 1], v, a0);
            a1 = fmaf(W[1 * wstride + c - 1], v, a1);
            a2 = fmaf(W[2 * wstride + c - 1], v, a2);
        }
        float e0 = __expf(a0 + g_slog[0 * L + l]);
        float e1 = __expf(a1 + g_slog[1 * L + l]);
        float e2 = __expf(a2 + g_slog[2 * L + l]);
        float num = ss_hmm[0 * L + l] * e0 + ss_hmm[1 * L + l] * e1
                  + ss_hmm[2 * L + l] * e2;
        if (mx > x0) { contrib += num / (e0 + e1 + e2); cnt += 1.f; }
    }
    #pragma unroll
    for (int off = 16; off > 0; off >>= 1) {
        contrib += __shfl_down_sync(0xffffffffu, contrib, off);
        cnt     += __shfl_down_sync(0xffffffffu, cnt, off);
    }
    __shared__ float rs[2][32];
    int nw = (blockDim.x + 31) >> 5;
    if ((t & 31) == 0) { rs[0][t >> 5] = contrib; rs[1][t >> 5] = cnt; }
    __syncthreads();
    if (t == 0) {
        float s = 0.f, c = 0.f;
        for (int w = 0; w < nw; ++w) { s += rs[0][w]; c += rs[1][w]; }
        out[b] = logf(s / c);
    }
}

extern "C" void kernel_launch(void* const* d_in, const int* in_sizes, int n_in,
                              void* d_out, int out_size)
{
    const float* x       = (const float*)d_in[0];   // [B, 21, L]
    const float* seq_hmm = (const float*)d_in[1];   // [H, L]
    const float* ss_hmm  = (const float*)d_in[2];   // [3, L]
    const float* W       = (const float*)d_in[3];   // [3, 20+H]
    const float* bvec    = (const float*)d_in[4];   // [3]
    float* out = (float*)d_out;

    const int B       = out_size;                   // 4096
    const int L       = in_sizes[2] / 3;            // 512
    const int H       = in_sizes[1] / L;            // 30
    const int C       = in_sizes[0] / (B * L);      // 21
    const int wstride = in_sizes[3] / 3;            // 20 + H = 50

    slog_kernel<<<(L + 255) / 256, 256>>>(seq_hmm, W, bvec, L, H, wstride);

    if ((L & 3) == 0 && L <= MAX_L) {
        if (C == 21)
            qpml_kernel<21><<<B, 128>>>(x, ss_hmm, W, out, L, C, wstride);
        else
            qpml_kernel<0><<<B, 128>>>(x, ss_hmm, W, out, L, C, wstride);
    } else {
        qpml_kernel_scalar<<<B, 128>>>(x, ss_hmm, W, out, L, C, wstride);
    }
}